// round 4
// baseline (speedup 1.0000x reference)
#include <cuda_runtime.h>
#include <cuda_bf16.h>
#include <cstdint>

// Problem constants (shapes are fixed by the reference)
#define NN      10000
#define EE      640000
#define TOT_E   (EE + NN)      // edges + self loops
#define IN_FT   512
#define OUT_FT  128

#define BM 32
#define BK 32
#define NKT (IN_FT / BK)       // 16 k-tiles
#define MAXD 512

// ---------------- device scratch (no allocation allowed) ----------------
__device__ float g_h[NN * OUT_FT];         // h = seq @ W_comb^T
__device__ float g_wcT[IN_FT * OUT_FT];    // W_comb transposed: [k][o]
__device__ float g_as[NN];                 // h @ att_src
__device__ float g_ad[NN];                 // h @ att_dst
__device__ int   g_cnt[NN];                // per-dst edge counts
__device__ int   g_rowptr[NN + 1];         // CSR row pointers (by dst)
__device__ int   g_fill[NN];               // scatter cursors
__device__ int   g_csr[TOT_E];             // src node id per CSR slot
__device__ int2  g_sd[TOT_E];              // decoded (src, dst)
__device__ int   g_flag = 0;               // 1 = edge_index is int32 (OR-only, monotonic)

// ---------------- helpers ----------------
__device__ __forceinline__ void cp16(void* dst, const void* src) {
    uint32_t d = (uint32_t)__cvta_generic_to_shared(dst);
    asm volatile("cp.async.cg.shared.global [%0], [%1], 16;\n" :: "r"(d), "l"(src));
}
__device__ __forceinline__ void cp_commit() {
    asm volatile("cp.async.commit_group;\n");
}
template<int N> __device__ __forceinline__ void cp_wait() {
    asm volatile("cp.async.wait_group %0;\n" :: "n"(N));
}

// ---------------- fused setup: wcomb + zero + dtype detect ----------------
// blocks [0, OUT_FT): W_combT[k][o] = sum_m W_gat[o][m] * W_fc[m][k]
// blocks [OUT_FT, ...): zero g_cnt, detect int32-vs-int64 edges
__global__ void setup_kernel(const float* __restrict__ Wgat,
                             const float* __restrict__ Wfc,
                             const int* __restrict__ ep, int E, int n) {
    if (blockIdx.x < OUT_FT) {
        __shared__ float wrow[OUT_FT];
        int o = blockIdx.x;
        int k = threadIdx.x;           // 0..511
        if (k < OUT_FT) wrow[k] = Wgat[o * OUT_FT + k];
        __syncthreads();
        float acc = 0.f;
#pragma unroll 8
        for (int m = 0; m < OUT_FT; m++)
            acc += wrow[m] * Wfc[m * IN_FT + k];
        g_wcT[k * OUT_FT + o] = acc;          // transposed store
    } else {
        int j = (blockIdx.x - OUT_FT) * blockDim.x + threadIdx.x;
        if (j < n) g_cnt[j] = 0;
        // int64 node ids < 2^31 have zero high words; int32 data has random ids there
        if (j < 1024 && j < E) {
            if (ep[2 * j + 1] != 0) atomicOr(&g_flag, 1);
        }
    }
}

// decode edges (2 per thread, vectorized), count degrees, stage (src,dst)
__global__ void count_kernel(const void* eidx, int E, int n) {
    int t = blockIdx.x * blockDim.x + threadIdx.x;
    int half = E >> 1;                 // E is even (640000)
    if (t < half) {
        int s0, d0, s1, d1;
        if (g_flag) {
            int2 ss = ((const int2*)eidx)[t];
            int2 dd = ((const int2*)((const int*)eidx + E))[t];
            s0 = ss.x; s1 = ss.y; d0 = dd.x; d1 = dd.y;
        } else {
            longlong2 ss = ((const longlong2*)eidx)[t];
            longlong2 dd = ((const longlong2*)((const long long*)eidx + E))[t];
            s0 = (int)ss.x; s1 = (int)ss.y; d0 = (int)dd.x; d1 = (int)dd.y;
        }
        *(int4*)&g_sd[2 * t] = make_int4(s0, d0, s1, d1);   // STG.128
        atomicAdd(&g_cnt[d0], 1);
        atomicAdd(&g_cnt[d1], 1);
    } else {
        int node = t - half;
        if (node < n) {                // self loops
            g_sd[E + node] = make_int2(node, node);
            atomicAdd(&g_cnt[node], 1);
        }
    }
}

// Single-block exclusive scan over g_cnt -> g_rowptr / g_fill
__global__ void scan_kernel(int n) {
    __shared__ int part[1024];
    int tid  = threadIdx.x;
    int per  = (n + 1023) / 1024;
    if (per > 16) per = 16;
    int base = tid * per;
    int loc[16];
    int sum = 0;
    for (int j = 0; j < per; j++) {
        int idx = base + j;
        int v = (idx < n) ? g_cnt[idx] : 0;
        loc[j] = sum;
        sum += v;
    }
    part[tid] = sum;
    __syncthreads();
    for (int off = 1; off < 1024; off <<= 1) {
        int v = (tid >= off) ? part[tid - off] : 0;
        __syncthreads();
        part[tid] += v;
        __syncthreads();
    }
    int excl = (tid == 0) ? 0 : part[tid - 1];
    for (int j = 0; j < per; j++) {
        int idx = base + j;
        if (idx < n) {
            int rp = excl + loc[j];
            g_rowptr[idx] = rp;
            g_fill[idx]   = rp;
        }
    }
    if (tid == 1023) g_rowptr[n] = part[1023];
}

// scatter srcs into CSR slots (2 edges per thread)
__global__ void scatter_kernel(int tot) {
    int t = blockIdx.x * blockDim.x + threadIdx.x;
    int half = tot >> 1;
    if (t < half) {
        int4 p = *(const int4*)&g_sd[2 * t];   // (s0,d0,s1,d1)
        int pos0 = atomicAdd(&g_fill[p.y], 1);
        g_csr[pos0] = p.x;
        int pos1 = atomicAdd(&g_fill[p.w], 1);
        g_csr[pos1] = p.z;
    } else if (2 * half + (t - half) < tot) {  // odd tail (tot even here, but safe)
        int2 p = g_sd[2 * half + (t - half)];
        int pos = atomicAdd(&g_fill[p.y], 1);
        g_csr[pos] = p.x;
    }
}

// h = seq @ W_comb^T.  BM=32 x BN=128 x BK=32, 64 threads, 8x8 microtile,
// cp.async double-buffered smem.  Fused epilogue computes a_s/a_d.
__global__ __launch_bounds__(64) void gemm_h_kernel(
        const float* __restrict__ seq,
        const float* __restrict__ att_s,
        const float* __restrict__ att_d, int n) {
    __shared__ float As[2][BM][36];      // pitch 36 floats (16B-aligned rows)
    __shared__ float Bs[2][BK][OUT_FT];

    int bm  = blockIdx.x * BM;
    int tid = threadIdx.x;               // 64 threads
    int cg  = tid & 15;                  // col group (16)
    int rg  = tid >> 4;                  // row group (4)
    int r0  = rg * 8;

    auto issue = [&](int kt, int buf) {
        int k0 = kt * BK;
#pragma unroll
        for (int i = 0; i < 4; i++) {                 // A: 32x32 = 256 x 16B
            int idx = tid + i * 64;
            int r = idx >> 3, c4 = (idx & 7) << 2;
            int row = bm + r; if (row >= n) row = n - 1;
            cp16(&As[buf][r][c4], &seq[row * IN_FT + k0 + c4]);
        }
#pragma unroll
        for (int i = 0; i < 16; i++) {                // B: 32x128 = 1024 x 16B
            int idx = tid + i * 64;
            int kk = idx >> 5, o4 = (idx & 31) << 2;
            cp16(&Bs[buf][kk][o4], &g_wcT[(k0 + kk) * OUT_FT + o4]);
        }
        cp_commit();
    };

    float acc[8][8];
#pragma unroll
    for (int i = 0; i < 8; i++)
#pragma unroll
        for (int j = 0; j < 8; j++) acc[i][j] = 0.f;

    issue(0, 0);
    issue(1, 1);

    for (int kt = 0; kt < NKT; kt++) {
        if (kt < NKT - 1) cp_wait<1>(); else cp_wait<0>();
        __syncthreads();
        int buf = kt & 1;
#pragma unroll
        for (int kk = 0; kk < BK; kk++) {
            float a[8];
#pragma unroll
            for (int i = 0; i < 8; i++) a[i] = As[buf][r0 + i][kk];  // broadcast
            float4 b0 = *(const float4*)&Bs[buf][kk][cg * 4];
            float4 b1 = *(const float4*)&Bs[buf][kk][64 + cg * 4];
            float b[8] = {b0.x, b0.y, b0.z, b0.w, b1.x, b1.y, b1.z, b1.w};
#pragma unroll
            for (int i = 0; i < 8; i++)
#pragma unroll
                for (int j = 0; j < 8; j++)
                    acc[i][j] += a[i] * b[j];
        }
        __syncthreads();
        if (kt + 2 < NKT) issue(kt + 2, buf);
    }

    // epilogue: store h + fused attention logits
    float as8[8], ad8[8];
#pragma unroll
    for (int j = 0; j < 4; j++) {
        as8[j]     = att_s[cg * 4 + j];
        as8[4 + j] = att_s[64 + cg * 4 + j];
        ad8[j]     = att_d[cg * 4 + j];
        ad8[4 + j] = att_d[64 + cg * 4 + j];
    }
#pragma unroll
    for (int i = 0; i < 8; i++) {
        int row = bm + r0 + i;
        bool valid = (row < n);
        float vs = 0.f, vd = 0.f;
#pragma unroll
        for (int j = 0; j < 8; j++) { vs += acc[i][j] * as8[j]; vd += acc[i][j] * ad8[j]; }
        if (valid) {
            *(float4*)&g_h[row * OUT_FT + cg * 4]      =
                make_float4(acc[i][0], acc[i][1], acc[i][2], acc[i][3]);
            *(float4*)&g_h[row * OUT_FT + 64 + cg * 4] =
                make_float4(acc[i][4], acc[i][5], acc[i][6], acc[i][7]);
        }
#pragma unroll
        for (int o = 1; o < 16; o <<= 1) {             // reduce over 16-lane group
            vs += __shfl_xor_sync(0xffffffffu, vs, o);
            vd += __shfl_xor_sync(0xffffffffu, vd, o);
        }
        if (valid && cg == 0) { g_as[row] = vs; g_ad[row] = vd; }
    }
}

// One block (128 threads) per destination node: segment softmax + weighted sum.
__global__ __launch_bounds__(128) void aggregate_kernel(
        const float* __restrict__ gat_bias,
        const float* __restrict__ bias,
        const float* __restrict__ prelu_a,
        float* __restrict__ out, int n) {
    int d = blockIdx.x;
    if (d >= n) return;
    int tid   = threadIdx.x;
    int w     = tid >> 5, lane = tid & 31;
    int start = g_rowptr[d];
    int end   = g_rowptr[d + 1];
    int deg   = end - start;
    float ad  = g_ad[d];

    __shared__ float e_sh[MAXD];
    __shared__ int   s_sh[MAXD];
    __shared__ float red[4];
    __shared__ float accsh[4][OUT_FT];

    if (deg <= MAXD) {
        // load + leaky-relu + max
        float lm = -1e30f;
        for (int i = tid; i < deg; i += 128) {
            int s = g_csr[start + i];
            float e = g_as[s] + ad;
            e = (e >= 0.f) ? e : 0.2f * e;
            s_sh[i] = s; e_sh[i] = e;
            lm = fmaxf(lm, e);
        }
#pragma unroll
        for (int o = 16; o > 0; o >>= 1)
            lm = fmaxf(lm, __shfl_xor_sync(0xffffffffu, lm, o));
        if (lane == 0) red[w] = lm;
        __syncthreads();
        float m = fmaxf(fmaxf(red[0], red[1]), fmaxf(red[2], red[3]));
        __syncthreads();

        // exp + denom
        float ls = 0.f;
        for (int i = tid; i < deg; i += 128) {
            float p = __expf(e_sh[i] - m);
            e_sh[i] = p;
            ls += p;
        }
#pragma unroll
        for (int o = 16; o > 0; o >>= 1)
            ls += __shfl_xor_sync(0xffffffffu, ls, o);
        if (lane == 0) red[w] = ls;
        __syncthreads();
        float denom = red[0] + red[1] + red[2] + red[3];

        // warp-parallel accumulation: warp w takes edges w, w+4, ...; lane = 4 features
        float4 a4 = make_float4(0.f, 0.f, 0.f, 0.f);
        for (int j = w; j < deg; j += 4) {
            float p = e_sh[j];
            const float4 hv = *(const float4*)&g_h[s_sh[j] * OUT_FT + lane * 4];
            a4.x += p * hv.x; a4.y += p * hv.y; a4.z += p * hv.z; a4.w += p * hv.w;
        }
        *(float4*)&accsh[w][lane * 4] = a4;
        __syncthreads();
        float sum = accsh[0][tid] + accsh[1][tid] + accsh[2][tid] + accsh[3][tid];

        float o_ = sum / (denom + 1e-16f) + gat_bias[tid] + bias[tid];
        float a  = prelu_a[0];
        out[d * OUT_FT + tid] = (o_ >= 0.f) ? o_ : a * o_;
    } else {
        // generic fallback: feature-per-thread, chunked path
        float lm = -1e30f;
        for (int i = start + tid; i < end; i += 128) {
            float e = g_as[g_csr[i]] + ad;
            e = (e >= 0.f) ? e : 0.2f * e;
            lm = fmaxf(lm, e);
        }
#pragma unroll
        for (int o = 16; o > 0; o >>= 1)
            lm = fmaxf(lm, __shfl_xor_sync(0xffffffffu, lm, o));
        if (lane == 0) red[w] = lm;
        __syncthreads();
        float m = fmaxf(fmaxf(red[0], red[1]), fmaxf(red[2], red[3]));
        __syncthreads();

        float ls = 0.f;
        for (int i = start + tid; i < end; i += 128) {
            float e = g_as[g_csr[i]] + ad;
            e = (e >= 0.f) ? e : 0.2f * e;
            ls += __expf(e - m);
        }
#pragma unroll
        for (int o = 16; o > 0; o >>= 1)
            ls += __shfl_xor_sync(0xffffffffu, ls, o);
        if (lane == 0) red[w] = ls;
        __syncthreads();
        float denom = red[0] + red[1] + red[2] + red[3];
        __syncthreads();

        float acc = 0.f;
        for (int c = start; c < end; c += 128) {
            int i = c + tid;
            if (i < end) {
                int s = g_csr[i];
                float e = g_as[s] + ad;
                e = (e >= 0.f) ? e : 0.2f * e;
                e_sh[tid] = __expf(e - m);
                s_sh[tid] = s;
            }
            __syncthreads();
            int len = min(128, end - c);
            for (int j = 0; j < len; j++)
                acc += e_sh[j] * g_h[s_sh[j] * OUT_FT + tid];
            __syncthreads();
        }
        float o_ = acc / (denom + 1e-16f) + gat_bias[tid] + bias[tid];
        float a  = prelu_a[0];
        out[d * OUT_FT + tid] = (o_ >= 0.f) ? o_ : a * o_;
    }
}

// ---------------- launch ----------------
extern "C" void kernel_launch(void* const* d_in, const int* in_sizes, int n_in,
                              void* d_out, int out_size) {
    const float* seq      = (const float*)d_in[0];
    const void*  eidx     = d_in[1];
    const float* Wfc      = (const float*)d_in[2];
    const float* Wgat     = (const float*)d_in[3];
    const float* att_src  = (const float*)d_in[4];
    const float* att_dst  = (const float*)d_in[5];
    const float* gat_bias = (const float*)d_in[6];
    const float* bias     = (const float*)d_in[7];
    const float* prelu_a  = (const float*)d_in[8];
    float* out = (float*)d_out;

    int n = in_sizes[0] / IN_FT;     // 10000
    int E = in_sizes[1] / 2;         // 640000
    int tot = E + n;

    int aux_blocks = (n + 511) / 512;
    setup_kernel<<<OUT_FT + aux_blocks, 512>>>(Wgat, Wfc, (const int*)eidx, E, n);
    int cnt_threads = E / 2 + n;
    count_kernel<<<(cnt_threads + 255) / 256, 256>>>(eidx, E, n);
    gemm_h_kernel<<<(n + BM - 1) / BM, 64>>>(seq, att_src, att_dst, n);
    scan_kernel<<<1, 1024>>>(n);
    int sc_threads = tot / 2 + 1;
    scatter_kernel<<<(sc_threads + 255) / 256, 256>>>(tot);
    aggregate_kernel<<<n, 128>>>(gat_bias, bias, prelu_a, out, n);
}

// round 6
// speedup vs baseline: 1.0933x; 1.0933x over previous
#include <cuda_runtime.h>
#include <cuda_bf16.h>
#include <cstdint>

// Problem constants (shapes are fixed by the reference)
#define NN      10000
#define EE      640000
#define TOT_E   (EE + NN)      // edges + self loops
#define IN_FT   512
#define OUT_FT  128

#define BM 32
#define BK 32
#define NKT (IN_FT / BK)       // 16 k-tiles
#define MAXD 512
#define SCAN_PER 40            // elements per thread in scan
#define SCAN_TOT (256 * SCAN_PER)   // 10240 >= NN; g_cnt sized to this exactly

// ---------------- device scratch (no allocation allowed) ----------------
__device__ float g_h[NN * OUT_FT];         // h = seq @ W_comb^T
__device__ float g_wcT[IN_FT * OUT_FT];    // W_comb transposed: [k][o]
__device__ float g_as[NN];                 // h @ att_src
__device__ float g_ad[NN];                 // h @ att_dst
__device__ int   g_cnt[SCAN_TOT];          // per-dst edge counts, padded to scan reach
__device__ int   g_rowptr[NN + 1];         // CSR row pointers (by dst)
__device__ int   g_fill[NN];               // scatter cursors
__device__ int   g_csr[TOT_E];             // src node id per CSR slot
__device__ int2  g_sd[TOT_E];              // decoded (src, dst)
__device__ int   g_flag = 0;               // 1 = edge_index is int32 (OR-only, monotonic)

// ---------------- helpers ----------------
__device__ __forceinline__ void cp16(void* dst, const void* src) {
    uint32_t d = (uint32_t)__cvta_generic_to_shared(dst);
    asm volatile("cp.async.cg.shared.global [%0], [%1], 16;\n" :: "r"(d), "l"(src));
}
__device__ __forceinline__ void cp_commit() {
    asm volatile("cp.async.commit_group;\n");
}
template<int N> __device__ __forceinline__ void cp_wait() {
    asm volatile("cp.async.wait_group %0;\n" :: "n"(N));
}

// ---------------- fused setup: wcomb + zero + dtype detect ----------------
__global__ void setup_kernel(const float* __restrict__ Wgat,
                             const float* __restrict__ Wfc,
                             const int* __restrict__ ep, int E, int n) {
    if (blockIdx.x < OUT_FT) {
        __shared__ float wrow[OUT_FT];
        int o = blockIdx.x;
        int k = threadIdx.x;           // 0..511
        if (k < OUT_FT) wrow[k] = Wgat[o * OUT_FT + k];
        __syncthreads();
        float acc = 0.f;
#pragma unroll 8
        for (int m = 0; m < OUT_FT; m++)
            acc += wrow[m] * Wfc[m * IN_FT + k];
        g_wcT[k * OUT_FT + o] = acc;          // transposed store
    } else {
        int j = (blockIdx.x - OUT_FT) * blockDim.x + threadIdx.x;
        if (j < SCAN_TOT) g_cnt[j] = 0;       // zero FULL padded array
        // int64 node ids < 2^31 have zero high words; int32 data has random ids there
        if (j < 1024 && j < E) {
            if (ep[2 * j + 1] != 0) atomicOr(&g_flag, 1);
        }
    }
}

// decode edges (2 per thread, vectorized), count degrees, stage (src,dst)
__global__ void count_kernel(const void* eidx, int E, int n) {
    int t = blockIdx.x * blockDim.x + threadIdx.x;
    int half = E >> 1;                 // E is even (640000)
    if (t < half) {
        int s0, d0, s1, d1;
        if (g_flag) {
            int2 ss = ((const int2*)eidx)[t];
            int2 dd = ((const int2*)((const int*)eidx + E))[t];
            s0 = ss.x; s1 = ss.y; d0 = dd.x; d1 = dd.y;
        } else {
            longlong2 ss = ((const longlong2*)eidx)[t];
            longlong2 dd = ((const longlong2*)((const long long*)eidx + E))[t];
            s0 = (int)ss.x; s1 = (int)ss.y; d0 = (int)dd.x; d1 = (int)dd.y;
        }
        *(int4*)&g_sd[2 * t] = make_int4(s0, d0, s1, d1);   // STG.128
        atomicAdd(&g_cnt[d0], 1);
        atomicAdd(&g_cnt[d1], 1);
    } else {
        int node = t - half;
        if (node < n) {                // self loops
            g_sd[E + node] = make_int2(node, node);
            atomicAdd(&g_cnt[node], 1);
        }
    }
}

// Single-block register-resident scan: 256 threads x 40 elems, 2 barriers.
// g_cnt is sized exactly SCAN_TOT and fully zeroed, so all reads are in-bounds
// and padding contributes 0.
__global__ __launch_bounds__(256) void scan_kernel(int n) {
    __shared__ int wsum[8];
    __shared__ int woff[8];
    int tid  = threadIdx.x;
    int lane = tid & 31, w = tid >> 5;
    int base = tid * SCAN_PER;

    int v[SCAN_PER];
#pragma unroll
    for (int q = 0; q < SCAN_PER / 4; q++) {
        int4 x = *(const int4*)&g_cnt[base + q * 4];
        v[q * 4 + 0] = x.x; v[q * 4 + 1] = x.y;
        v[q * 4 + 2] = x.z; v[q * 4 + 3] = x.w;
    }
    int s = 0;
#pragma unroll
    for (int j = 0; j < SCAN_PER; j++) s += v[j];

    // inclusive warp scan of per-thread sums
    int incl = s;
#pragma unroll
    for (int o = 1; o < 32; o <<= 1) {
        int t2 = __shfl_up_sync(0xffffffffu, incl, o);
        if (lane >= o) incl += t2;
    }
    if (lane == 31) wsum[w] = incl;
    __syncthreads();
    if (w == 0 && lane < 8) {
        int ws = wsum[lane];
        int wi = ws;
#pragma unroll
        for (int o = 1; o < 8; o <<= 1) {
            int t2 = __shfl_up_sync(0xffu, wi, o);
            if (lane >= o) wi += t2;
        }
        woff[lane] = wi - ws;              // exclusive warp offset
        if (lane == 7) g_rowptr[n] = wi;   // grand total
    }
    __syncthreads();

    int run = woff[w] + (incl - s);    // exclusive prefix for this thread
#pragma unroll
    for (int j = 0; j < SCAN_PER; j++) {
        int idx = base + j;
        if (idx < n) {
            g_rowptr[idx] = run;
            g_fill[idx]   = run;
        }
        run += v[j];
    }
}

// scatter srcs into CSR slots (2 edges per thread)
__global__ void scatter_kernel(int tot) {
    int t = blockIdx.x * blockDim.x + threadIdx.x;
    int half = tot >> 1;
    if (t < half) {
        int4 p = *(const int4*)&g_sd[2 * t];   // (s0,d0,s1,d1)
        int pos0 = atomicAdd(&g_fill[p.y], 1);
        g_csr[pos0] = p.x;
        int pos1 = atomicAdd(&g_fill[p.w], 1);
        g_csr[pos1] = p.z;
    } else if (2 * half + (t - half) < tot) {  // odd tail
        int2 p = g_sd[2 * half + (t - half)];
        int pos = atomicAdd(&g_fill[p.y], 1);
        g_csr[pos] = p.x;
    }
}

// h = seq @ W_comb^T.  BM=32 x 128 x BK=32, 128 threads, 4x8 microtile,
// cp.async double-buffered smem.  Fused epilogue computes a_s/a_d.
__global__ __launch_bounds__(128, 4) void gemm_h_kernel(
        const float* __restrict__ seq,
        const float* __restrict__ att_s,
        const float* __restrict__ att_d, int n) {
    __shared__ float As[2][BM][36];      // pitch 36 floats (16B-aligned rows)
    __shared__ float Bs[2][BK][OUT_FT];

    int bm  = blockIdx.x * BM;
    int tid = threadIdx.x;
    int tx  = tid & 15;          // col group
    int ty  = tid >> 4;          // 0..7 -> 4 rows each
    int r0  = ty * 4;

    auto issue = [&](int kt, int buf) {
        int k0 = kt * BK;
#pragma unroll
        for (int i = 0; i < 2; i++) {                 // A: 32x32 = 256 x 16B
            int idx = tid + i * 128;
            int r = idx >> 3, c4 = (idx & 7) << 2;
            int row = bm + r; if (row >= n) row = n - 1;
            cp16(&As[buf][r][c4], &seq[row * IN_FT + k0 + c4]);
        }
#pragma unroll
        for (int i = 0; i < 8; i++) {                 // B: 32x128 = 1024 x 16B
            int idx = tid + i * 128;
            int kk = idx >> 5, o4 = (idx & 31) << 2;
            cp16(&Bs[buf][kk][o4], &g_wcT[(k0 + kk) * OUT_FT + o4]);
        }
        cp_commit();
    };

    float acc[4][8];
#pragma unroll
    for (int i = 0; i < 4; i++)
#pragma unroll
        for (int j = 0; j < 8; j++) acc[i][j] = 0.f;

    issue(0, 0);
    issue(1, 1);

    for (int kt = 0; kt < NKT; kt++) {
        if (kt < NKT - 1) cp_wait<1>(); else cp_wait<0>();
        __syncthreads();
        int buf = kt & 1;
#pragma unroll
        for (int kk = 0; kk < BK; kk++) {
            float a[4];
#pragma unroll
            for (int i = 0; i < 4; i++) a[i] = As[buf][r0 + i][kk];
            // thread's 8 cols: {tx*4..+3} and {64+tx*4..+3} (conflict-free LDS.128)
            float4 b0 = *(const float4*)&Bs[buf][kk][tx * 4];
            float4 b1 = *(const float4*)&Bs[buf][kk][64 + tx * 4];
            float b[8] = {b0.x, b0.y, b0.z, b0.w, b1.x, b1.y, b1.z, b1.w};
#pragma unroll
            for (int i = 0; i < 4; i++)
#pragma unroll
                for (int j = 0; j < 8; j++)
                    acc[i][j] += a[i] * b[j];
        }
        __syncthreads();
        if (kt + 2 < NKT) issue(kt + 2, buf);
    }

    // epilogue: store h + fused attention logits
    float as8[8], ad8[8];
#pragma unroll
    for (int j = 0; j < 4; j++) {
        as8[j]     = att_s[tx * 4 + j];
        as8[4 + j] = att_s[64 + tx * 4 + j];
        ad8[j]     = att_d[tx * 4 + j];
        ad8[4 + j] = att_d[64 + tx * 4 + j];
    }
#pragma unroll
    for (int i = 0; i < 4; i++) {
        int row = bm + r0 + i;
        bool valid = (row < n);
        float vs = 0.f, vd = 0.f;
#pragma unroll
        for (int j = 0; j < 8; j++) { vs += acc[i][j] * as8[j]; vd += acc[i][j] * ad8[j]; }
        if (valid) {
            *(float4*)&g_h[row * OUT_FT + tx * 4]      =
                make_float4(acc[i][0], acc[i][1], acc[i][2], acc[i][3]);
            *(float4*)&g_h[row * OUT_FT + 64 + tx * 4] =
                make_float4(acc[i][4], acc[i][5], acc[i][6], acc[i][7]);
        }
#pragma unroll
        for (int o = 1; o < 16; o <<= 1) {
            vs += __shfl_xor_sync(0xffffffffu, vs, o);
            vd += __shfl_xor_sync(0xffffffffu, vd, o);
        }
        if (valid && tx == 0) { g_as[row] = vs; g_ad[row] = vd; }
    }
}

// One block (128 threads) per destination node: segment softmax + weighted sum.
__global__ __launch_bounds__(128) void aggregate_kernel(
        const float* __restrict__ gat_bias,
        const float* __restrict__ bias,
        const float* __restrict__ prelu_a,
        float* __restrict__ out, int n) {
    int d = blockIdx.x;
    if (d >= n) return;
    int tid   = threadIdx.x;
    int w     = tid >> 5, lane = tid & 31;
    int start = g_rowptr[d];
    int end   = g_rowptr[d + 1];
    int deg   = end - start;
    float ad  = g_ad[d];

    __shared__ float e_sh[MAXD];
    __shared__ int   s_sh[MAXD];
    __shared__ float red[4];
    __shared__ float accsh[4][OUT_FT];

    if (deg <= MAXD) {
        // load + leaky-relu + max
        float lm = -1e30f;
        for (int i = tid; i < deg; i += 128) {
            int s = g_csr[start + i];
            float e = g_as[s] + ad;
            e = (e >= 0.f) ? e : 0.2f * e;
            s_sh[i] = s; e_sh[i] = e;
            lm = fmaxf(lm, e);
        }
#pragma unroll
        for (int o = 16; o > 0; o >>= 1)
            lm = fmaxf(lm, __shfl_xor_sync(0xffffffffu, lm, o));
        if (lane == 0) red[w] = lm;
        __syncthreads();
        float m = fmaxf(fmaxf(red[0], red[1]), fmaxf(red[2], red[3]));
        __syncthreads();

        // exp + denom
        float ls = 0.f;
        for (int i = tid; i < deg; i += 128) {
            float p = __expf(e_sh[i] - m);
            e_sh[i] = p;
            ls += p;
        }
#pragma unroll
        for (int o = 16; o > 0; o >>= 1)
            ls += __shfl_xor_sync(0xffffffffu, ls, o);
        if (lane == 0) red[w] = ls;
        __syncthreads();
        float denom = red[0] + red[1] + red[2] + red[3];

        // warp-parallel accumulation: warp w takes edges w, w+4, ...; lane = 4 features
        float4 a4 = make_float4(0.f, 0.f, 0.f, 0.f);
        for (int j = w; j < deg; j += 4) {
            float p = e_sh[j];
            const float4 hv = *(const float4*)&g_h[s_sh[j] * OUT_FT + lane * 4];
            a4.x += p * hv.x; a4.y += p * hv.y; a4.z += p * hv.z; a4.w += p * hv.w;
        }
        *(float4*)&accsh[w][lane * 4] = a4;
        __syncthreads();
        float sum = accsh[0][tid] + accsh[1][tid] + accsh[2][tid] + accsh[3][tid];

        float o_ = sum / (denom + 1e-16f) + gat_bias[tid] + bias[tid];
        float a  = prelu_a[0];
        out[d * OUT_FT + tid] = (o_ >= 0.f) ? o_ : a * o_;
    } else {
        // generic fallback: feature-per-thread, chunked path
        float lm = -1e30f;
        for (int i = start + tid; i < end; i += 128) {
            float e = g_as[g_csr[i]] + ad;
            e = (e >= 0.f) ? e : 0.2f * e;
            lm = fmaxf(lm, e);
        }
#pragma unroll
        for (int o = 16; o > 0; o >>= 1)
            lm = fmaxf(lm, __shfl_xor_sync(0xffffffffu, lm, o));
        if (lane == 0) red[w] = lm;
        __syncthreads();
        float m = fmaxf(fmaxf(red[0], red[1]), fmaxf(red[2], red[3]));
        __syncthreads();

        float ls = 0.f;
        for (int i = start + tid; i < end; i += 128) {
            float e = g_as[g_csr[i]] + ad;
            e = (e >= 0.f) ? e : 0.2f * e;
            ls += __expf(e - m);
        }
#pragma unroll
        for (int o = 16; o > 0; o >>= 1)
            ls += __shfl_xor_sync(0xffffffffu, ls, o);
        if (lane == 0) red[w] = ls;
        __syncthreads();
        float denom = red[0] + red[1] + red[2] + red[3];
        __syncthreads();

        float acc = 0.f;
        for (int c = start; c < end; c += 128) {
            int i = c + tid;
            if (i < end) {
                int s = g_csr[i];
                float e = g_as[s] + ad;
                e = (e >= 0.f) ? e : 0.2f * e;
                e_sh[tid] = __expf(e - m);
                s_sh[tid] = s;
            }
            __syncthreads();
            int len = min(128, end - c);
            for (int j = 0; j < len; j++)
                acc += e_sh[j] * g_h[s_sh[j] * OUT_FT + tid];
            __syncthreads();
        }
        float o_ = acc / (denom + 1e-16f) + gat_bias[tid] + bias[tid];
        float a  = prelu_a[0];
        out[d * OUT_FT + tid] = (o_ >= 0.f) ? o_ : a * o_;
    }
}

// ---------------- launch ----------------
extern "C" void kernel_launch(void* const* d_in, const int* in_sizes, int n_in,
                              void* d_out, int out_size) {
    const float* seq      = (const float*)d_in[0];
    const void*  eidx     = d_in[1];
    const float* Wfc      = (const float*)d_in[2];
    const float* Wgat     = (const float*)d_in[3];
    const float* att_src  = (const float*)d_in[4];
    const float* att_dst  = (const float*)d_in[5];
    const float* gat_bias = (const float*)d_in[6];
    const float* bias     = (const float*)d_in[7];
    const float* prelu_a  = (const float*)d_in[8];
    float* out = (float*)d_out;

    int n = in_sizes[0] / IN_FT;     // 10000
    int E = in_sizes[1] / 2;         // 640000
    int tot = E + n;

    int aux_blocks = (SCAN_TOT + 511) / 512;   // zero the FULL padded g_cnt
    setup_kernel<<<OUT_FT + aux_blocks, 512>>>(Wgat, Wfc, (const int*)eidx, E, n);
    int cnt_threads = E / 2 + n;
    count_kernel<<<(cnt_threads + 255) / 256, 256>>>(eidx, E, n);
    gemm_h_kernel<<<(n + BM - 1) / BM, 128>>>(seq, att_src, att_dst, n);
    scan_kernel<<<1, 256>>>(n);
    int sc_threads = tot / 2 + 1;
    scatter_kernel<<<(sc_threads + 255) / 256, 256>>>(tot);
    aggregate_kernel<<<n, 128>>>(gat_bias, bias, prelu_a, out, n);
}

// round 8
// speedup vs baseline: 1.1774x; 1.0769x over previous
#include <cuda_runtime.h>
#include <cuda_bf16.h>
#include <cstdint>

// Problem constants (shapes are fixed by the reference)
#define NN      10000
#define EE      640000
#define TOT_E   (EE + NN)      // edges + self loops
#define IN_FT   512
#define OUT_FT  128

#define BM 32
#define BK 32
#define NKT (IN_FT / BK)       // 16 k-tiles
#define MAXD 512
#define SCAN_TOT 10240         // padded count array (40 * 256 >= NN)
#define NBLK 40                // scan blocks

// ---------------- device scratch (no allocation allowed) ----------------
__device__ float g_h[NN * OUT_FT];         // h = seq @ W_comb^T
__device__ float g_wcT[IN_FT * OUT_FT];    // W_comb transposed: [k][o]
__device__ float g_as[NN];                 // h @ att_src
__device__ float g_ad[NN];                 // h @ att_dst
__device__ int   g_cnt[SCAN_TOT];          // per-dst edge counts, padded
__device__ int   g_rowptr[NN + 1];         // block-LOCAL exclusive prefixes
__device__ int   g_fill[NN];               // scatter cursors (block-local)
__device__ int   g_blktot[NBLK];           // per-scan-block totals
__device__ int   g_blkoff[NBLK];           // exclusive scan of block totals
__device__ unsigned g_ticket;              // last-block ticket (zeroed in setup)
__device__ int   g_csr[TOT_E];             // src node id per CSR slot
__device__ int2  g_sd[TOT_E];              // decoded (src, dst)
__device__ int   g_flag = 0;               // 1 = edge_index is int32 (OR-only)

// ---------------- helpers ----------------
__device__ __forceinline__ void cp16(void* dst, const void* src) {
    uint32_t d = (uint32_t)__cvta_generic_to_shared(dst);
    asm volatile("cp.async.cg.shared.global [%0], [%1], 16;\n" :: "r"(d), "l"(src));
}
__device__ __forceinline__ void cp_commit() {
    asm volatile("cp.async.commit_group;\n");
}
template<int N> __device__ __forceinline__ void cp_wait() {
    asm volatile("cp.async.wait_group %0;\n" :: "n"(N));
}

// ---------------- fused setup: wcomb + zero + dtype detect ----------------
__global__ void setup_kernel(const float* __restrict__ Wgat,
                             const float* __restrict__ Wfc,
                             const int* __restrict__ ep, int E, int n) {
    if (blockIdx.x < OUT_FT) {
        __shared__ float wrow[OUT_FT];
        int o = blockIdx.x;
        int k = threadIdx.x;           // 0..511
        if (k < OUT_FT) wrow[k] = Wgat[o * OUT_FT + k];
        __syncthreads();
        float acc = 0.f;
#pragma unroll 8
        for (int m = 0; m < OUT_FT; m++)
            acc += wrow[m] * Wfc[m * IN_FT + k];
        g_wcT[k * OUT_FT + o] = acc;          // transposed store
    } else {
        int j = (blockIdx.x - OUT_FT) * blockDim.x + threadIdx.x;
        if (j < SCAN_TOT) g_cnt[j] = 0;       // zero FULL padded array
        if (j == 0) g_ticket = 0;
        // int64 node ids < 2^31 have zero high words; int32 data has random ids there
        if (j < 1024 && j < E) {
            if (ep[2 * j + 1] != 0) atomicOr(&g_flag, 1);
        }
    }
}

// decode edges (4 per thread, vectorized), count degrees, stage (src,dst)
__global__ void count_kernel(const void* eidx, int E, int n) {
    int t = blockIdx.x * blockDim.x + threadIdx.x;
    int quarter = E >> 2;              // E % 4 == 0 for this dataset; tail handled below
    int rem = E & 3;
    if (t < quarter) {
        int s[4], d[4];
        if (g_flag) {
            int4 ss = ((const int4*)eidx)[t];
            int4 dd = ((const int4*)((const int*)eidx + E))[t];
            s[0] = ss.x; s[1] = ss.y; s[2] = ss.z; s[3] = ss.w;
            d[0] = dd.x; d[1] = dd.y; d[2] = dd.z; d[3] = dd.w;
        } else {
            const longlong2* sp = (const longlong2*)eidx;
            const longlong2* dp = (const longlong2*)((const long long*)eidx + E);
            longlong2 s01 = sp[2 * t], s23 = sp[2 * t + 1];
            longlong2 d01 = dp[2 * t], d23 = dp[2 * t + 1];
            s[0] = (int)s01.x; s[1] = (int)s01.y; s[2] = (int)s23.x; s[3] = (int)s23.y;
            d[0] = (int)d01.x; d[1] = (int)d01.y; d[2] = (int)d23.x; d[3] = (int)d23.y;
        }
        *(int4*)&g_sd[4 * t]     = make_int4(s[0], d[0], s[1], d[1]);
        *(int4*)&g_sd[4 * t + 2] = make_int4(s[2], d[2], s[3], d[3]);
        atomicAdd(&g_cnt[d[0]], 1);
        atomicAdd(&g_cnt[d[1]], 1);
        atomicAdd(&g_cnt[d[2]], 1);
        atomicAdd(&g_cnt[d[3]], 1);
    } else if (t < quarter + rem) {
        int e = E - rem + (t - quarter);
        int s, d;
        if (g_flag) {
            const int* q = (const int*)eidx;
            s = q[e]; d = q[E + e];
        } else {
            const long long* q = (const long long*)eidx;
            s = (int)q[e]; d = (int)q[E + e];
        }
        g_sd[e] = make_int2(s, d);
        atomicAdd(&g_cnt[d], 1);
    } else {
        int node = t - quarter - rem;
        if (node < n) {                // self loops
            g_sd[E + node] = make_int2(node, node);
            atomicAdd(&g_cnt[node], 1);
        }
    }
}

// 40-block scan: each block scans its 256 counts (block-local exclusive
// prefixes into g_rowptr/g_fill), last block (ticket) scans the 40 totals.
__global__ __launch_bounds__(256) void scan_kernel(int n) {
    __shared__ int wsum[8];
    __shared__ int lastflag;
    int b = blockIdx.x, t = threadIdx.x;
    int lane = t & 31, w = t >> 5;
    int idx = b * 256 + t;

    int v = g_cnt[idx];
    // inclusive warp scan
    int incl = v;
#pragma unroll
    for (int o = 1; o < 32; o <<= 1) {
        int x = __shfl_up_sync(0xffffffffu, incl, o);
        if (lane >= o) incl += x;
    }
    if (lane == 31) wsum[w] = incl;
    __syncthreads();
    int woff = 0;
#pragma unroll
    for (int j = 0; j < 8; j++) woff += (j < w) ? wsum[j] : 0;
    int excl = woff + incl - v;        // block-local exclusive prefix

    if (idx <= n) g_rowptr[idx] = excl;
    if (idx < n)  g_fill[idx]   = excl;

    // block total -> last block computes block offsets
    if (t == 0) {
        int tot = 0;
#pragma unroll
        for (int j = 0; j < 8; j++) tot += wsum[j];
        g_blktot[b] = tot;
        __threadfence();
        unsigned tk = atomicAdd(&g_ticket, 1u);
        lastflag = (tk == NBLK - 1);
    }
    __syncthreads();
    if (lastflag && t == 0) {
        int run = 0;
#pragma unroll
        for (int j = 0; j < NBLK; j++) {
            g_blkoff[j] = run;
            run += g_blktot[j];
        }
    }
}

// scatter srcs into CSR slots (2 edges per thread); global pos = local + blkoff
__global__ void scatter_kernel(int tot) {
    int t = blockIdx.x * blockDim.x + threadIdx.x;
    int half = tot >> 1;
    if (t < half) {
        int4 p = *(const int4*)&g_sd[2 * t];   // (s0,d0,s1,d1)
        int pos0 = atomicAdd(&g_fill[p.y], 1) + g_blkoff[p.y >> 8];
        g_csr[pos0] = p.x;
        int pos1 = atomicAdd(&g_fill[p.w], 1) + g_blkoff[p.w >> 8];
        g_csr[pos1] = p.z;
    } else if (2 * half + (t - half) < tot) {  // odd tail
        int2 p = g_sd[2 * half + (t - half)];
        int pos = atomicAdd(&g_fill[p.y], 1) + g_blkoff[p.y >> 8];
        g_csr[pos] = p.x;
    }
}

// h = seq @ W_comb^T.  BM=32 x 128 x BK=32, 128 threads, 4x8 microtile,
// cp.async double-buffered smem.  Fused epilogue computes a_s/a_d.
__global__ __launch_bounds__(128, 4) void gemm_h_kernel(
        const float* __restrict__ seq,
        const float* __restrict__ att_s,
        const float* __restrict__ att_d, int n) {
    __shared__ float As[2][BM][36];      // pitch 36 floats (16B-aligned rows)
    __shared__ float Bs[2][BK][OUT_FT];

    int bm  = blockIdx.x * BM;
    int tid = threadIdx.x;
    int tx  = tid & 15;          // col group
    int ty  = tid >> 4;          // 0..7 -> 4 rows each
    int r0  = ty * 4;

    auto issue = [&](int kt, int buf) {
        int k0 = kt * BK;
#pragma unroll
        for (int i = 0; i < 2; i++) {                 // A: 32x32 = 256 x 16B
            int idx = tid + i * 128;
            int r = idx >> 3, c4 = (idx & 7) << 2;
            int row = bm + r; if (row >= n) row = n - 1;
            cp16(&As[buf][r][c4], &seq[row * IN_FT + k0 + c4]);
        }
#pragma unroll
        for (int i = 0; i < 8; i++) {                 // B: 32x128 = 1024 x 16B
            int idx = tid + i * 128;
            int kk = idx >> 5, o4 = (idx & 31) << 2;
            cp16(&Bs[buf][kk][o4], &g_wcT[(k0 + kk) * OUT_FT + o4]);
        }
        cp_commit();
    };

    float acc[4][8];
#pragma unroll
    for (int i = 0; i < 4; i++)
#pragma unroll
        for (int j = 0; j < 8; j++) acc[i][j] = 0.f;

    issue(0, 0);
    issue(1, 1);

    for (int kt = 0; kt < NKT; kt++) {
        if (kt < NKT - 1) cp_wait<1>(); else cp_wait<0>();
        __syncthreads();
        int buf = kt & 1;
#pragma unroll
        for (int kk = 0; kk < BK; kk++) {
            float a[4];
#pragma unroll
            for (int i = 0; i < 4; i++) a[i] = As[buf][r0 + i][kk];
            // thread's 8 cols: {tx*4..+3} and {64+tx*4..+3} (conflict-free LDS.128)
            float4 b0 = *(const float4*)&Bs[buf][kk][tx * 4];
            float4 b1 = *(const float4*)&Bs[buf][kk][64 + tx * 4];
            float b[8] = {b0.x, b0.y, b0.z, b0.w, b1.x, b1.y, b1.z, b1.w};
#pragma unroll
            for (int i = 0; i < 4; i++)
#pragma unroll
                for (int j = 0; j < 8; j++)
                    acc[i][j] += a[i] * b[j];
        }
        __syncthreads();
        if (kt + 2 < NKT) issue(kt + 2, buf);
    }

    // epilogue: store h + fused attention logits
    float as8[8], ad8[8];
#pragma unroll
    for (int j = 0; j < 4; j++) {
        as8[j]     = att_s[tx * 4 + j];
        as8[4 + j] = att_s[64 + tx * 4 + j];
        ad8[j]     = att_d[tx * 4 + j];
        ad8[4 + j] = att_d[64 + tx * 4 + j];
    }
#pragma unroll
    for (int i = 0; i < 4; i++) {
        int row = bm + r0 + i;
        bool valid = (row < n);
        float vs = 0.f, vd = 0.f;
#pragma unroll
        for (int j = 0; j < 8; j++) { vs += acc[i][j] * as8[j]; vd += acc[i][j] * ad8[j]; }
        if (valid) {
            *(float4*)&g_h[row * OUT_FT + tx * 4]      =
                make_float4(acc[i][0], acc[i][1], acc[i][2], acc[i][3]);
            *(float4*)&g_h[row * OUT_FT + 64 + tx * 4] =
                make_float4(acc[i][4], acc[i][5], acc[i][6], acc[i][7]);
        }
#pragma unroll
        for (int o = 1; o < 16; o <<= 1) {
            vs += __shfl_xor_sync(0xffffffffu, vs, o);
            vd += __shfl_xor_sync(0xffffffffu, vd, o);
        }
        if (valid && tx == 0) { g_as[row] = vs; g_ad[row] = vd; }
    }
}

// One block (128 threads) per destination node: segment softmax + weighted sum.
__global__ __launch_bounds__(128) void aggregate_kernel(
        const float* __restrict__ gat_bias,
        const float* __restrict__ bias,
        const float* __restrict__ prelu_a,
        float* __restrict__ out, int n) {
    int d = blockIdx.x;
    if (d >= n) return;
    int tid   = threadIdx.x;
    int w     = tid >> 5, lane = tid & 31;
    int start = g_rowptr[d]     + g_blkoff[d >> 8];
    int end   = g_rowptr[d + 1] + g_blkoff[(d + 1) >> 8];
    int deg   = end - start;
    float ad  = g_ad[d];

    __shared__ float e_sh[MAXD];
    __shared__ int   s_sh[MAXD];
    __shared__ float red[4];
    __shared__ float accsh[4][OUT_FT];

    if (deg <= MAXD) {
        // load + leaky-relu + max
        float lm = -1e30f;
        for (int i = tid; i < deg; i += 128) {
            int s = g_csr[start + i];
            float e = g_as[s] + ad;
            e = (e >= 0.f) ? e : 0.2f * e;
            s_sh[i] = s; e_sh[i] = e;
            lm = fmaxf(lm, e);
        }
#pragma unroll
        for (int o = 16; o > 0; o >>= 1)
            lm = fmaxf(lm, __shfl_xor_sync(0xffffffffu, lm, o));
        if (lane == 0) red[w] = lm;
        __syncthreads();
        float m = fmaxf(fmaxf(red[0], red[1]), fmaxf(red[2], red[3]));
        __syncthreads();

        // exp + denom
        float ls = 0.f;
        for (int i = tid; i < deg; i += 128) {
            float p = __expf(e_sh[i] - m);
            e_sh[i] = p;
            ls += p;
        }
#pragma unroll
        for (int o = 16; o > 0; o >>= 1)
            ls += __shfl_xor_sync(0xffffffffu, ls, o);
        if (lane == 0) red[w] = ls;
        __syncthreads();
        float denom = red[0] + red[1] + red[2] + red[3];

        // warp-parallel accumulation: warp w takes edges w, w+4, ...; lane = 4 features
        float4 a4 = make_float4(0.f, 0.f, 0.f, 0.f);
        for (int j = w; j < deg; j += 4) {
            float p = e_sh[j];
            const float4 hv = *(const float4*)&g_h[s_sh[j] * OUT_FT + lane * 4];
            a4.x += p * hv.x; a4.y += p * hv.y; a4.z += p * hv.z; a4.w += p * hv.w;
        }
        *(float4*)&accsh[w][lane * 4] = a4;
        __syncthreads();
        float sum = accsh[0][tid] + accsh[1][tid] + accsh[2][tid] + accsh[3][tid];

        float o_ = sum / (denom + 1e-16f) + gat_bias[tid] + bias[tid];
        float a  = prelu_a[0];
        out[d * OUT_FT + tid] = (o_ >= 0.f) ? o_ : a * o_;
    } else {
        // generic fallback: feature-per-thread, chunked path
        float lm = -1e30f;
        for (int i = start + tid; i < end; i += 128) {
            float e = g_as[g_csr[i]] + ad;
            e = (e >= 0.f) ? e : 0.2f * e;
            lm = fmaxf(lm, e);
        }
#pragma unroll
        for (int o = 16; o > 0; o >>= 1)
            lm = fmaxf(lm, __shfl_xor_sync(0xffffffffu, lm, o));
        if (lane == 0) red[w] = lm;
        __syncthreads();
        float m = fmaxf(fmaxf(red[0], red[1]), fmaxf(red[2], red[3]));
        __syncthreads();

        float ls = 0.f;
        for (int i = start + tid; i < end; i += 128) {
            float e = g_as[g_csr[i]] + ad;
            e = (e >= 0.f) ? e : 0.2f * e;
            ls += __expf(e - m);
        }
#pragma unroll
        for (int o = 16; o > 0; o >>= 1)
            ls += __shfl_xor_sync(0xffffffffu, ls, o);
        if (lane == 0) red[w] = ls;
        __syncthreads();
        float denom = red[0] + red[1] + red[2] + red[3];
        __syncthreads();

        float acc = 0.f;
        for (int c = start; c < end; c += 128) {
            int i = c + tid;
            if (i < end) {
                int s = g_csr[i];
                float e = g_as[s] + ad;
                e = (e >= 0.f) ? e : 0.2f * e;
                e_sh[tid] = __expf(e - m);
                s_sh[tid] = s;
            }
            __syncthreads();
            int len = min(128, end - c);
            for (int j = 0; j < len; j++)
                acc += e_sh[j] * g_h[s_sh[j] * OUT_FT + tid];
            __syncthreads();
        }
        float o_ = acc / (denom + 1e-16f) + gat_bias[tid] + bias[tid];
        float a  = prelu_a[0];
        out[d * OUT_FT + tid] = (o_ >= 0.f) ? o_ : a * o_;
    }
}

// ---------------- launch ----------------
extern "C" void kernel_launch(void* const* d_in, const int* in_sizes, int n_in,
                              void* d_out, int out_size) {
    const float* seq      = (const float*)d_in[0];
    const void*  eidx     = d_in[1];
    const float* Wfc      = (const float*)d_in[2];
    const float* Wgat     = (const float*)d_in[3];
    const float* att_src  = (const float*)d_in[4];
    const float* att_dst  = (const float*)d_in[5];
    const float* gat_bias = (const float*)d_in[6];
    const float* bias     = (const float*)d_in[7];
    const float* prelu_a  = (const float*)d_in[8];
    float* out = (float*)d_out;

    int n = in_sizes[0] / IN_FT;     // 10000
    int E = in_sizes[1] / 2;         // 640000
    int tot = E + n;

    int aux_blocks = (SCAN_TOT + 511) / 512;   // zero the FULL padded g_cnt
    setup_kernel<<<OUT_FT + aux_blocks, 512>>>(Wgat, Wfc, (const int*)eidx, E, n);
    int cnt_threads = E / 4 + (E & 3) + n;
    count_kernel<<<(cnt_threads + 255) / 256, 256>>>(eidx, E, n);
    gemm_h_kernel<<<(n + BM - 1) / BM, 128>>>(seq, att_src, att_dst, n);
    scan_kernel<<<NBLK, 256>>>(n);
    int sc_threads = tot / 2 + 1;
    scatter_kernel<<<(sc_threads + 255) / 256, 256>>>(tot);
    aggregate_kernel<<<n, 128>>>(gat_bias, bias, prelu_a, out, n);
}